// round 17
// baseline (speedup 1.0000x reference)
#include <cuda_runtime.h>
#include <cuda_fp16.h>
#include <cstdint>

#define NB 128
#define NT 256          // 8 compute warps
#define BB 128
#define TT 1024
#define FF 64
#define HH 512

typedef unsigned long long ull;

// ---------------- device scratch ----------------
__device__ __align__(1024) unsigned char g_hh[2][8 * 16384];     // h fp16 chunk tiles
__device__ __align__(1024) unsigned char g_xh[(size_t)TT * 16384]; // x fp16 tiles
__device__ float g_hist[(size_t)TT * HH * BB];   // decoder-input h [kd][j][b]
__device__ float g_woutT[HH * FF];
__device__ unsigned int g_flag[64];              // [chunk 0..7][warp 0..7]
__device__ unsigned int g_count = 0, g_gen = 0;

// ---------------- smem byte offsets ----------------
#define OFF_WBE  0          // enc B frags: 9 ch * 2048 (fp16)
#define OFF_WBD  18432      // dec B frags: 8 ch * 2048
#define OFF_A    34816      // 3 stages * 16384
#define OFF_BE   83968      // 16 floats
#define OFF_BD   84032      // 16 floats
#define SMEM_BYTES 84096

static __device__ __forceinline__ uint32_t sw128(uint32_t o) {
    return o ^ ((o >> 3) & 0x70);
}
__device__ __forceinline__ float sigf(float x) {
    return __fdividef(1.0f, 1.0f + __expf(-x));
}
__device__ __forceinline__ float tanhfast(float x) {
    return 1.0f - __fdividef(2.0f, __expf(2.0f * x) + 1.0f);
}

__device__ __forceinline__ void grid_barrier_init() {
    __syncthreads();
    if (threadIdx.x == 0) {
        unsigned int cur0;
        asm volatile("ld.acquire.gpu.b32 %0, [%1];" : "=r"(cur0) : "l"(&g_gen) : "memory");
        unsigned int target = cur0 + 1u;
        __threadfence();
        unsigned int t = atomicAdd(&g_count, 1u);
        if (t == NB - 1u) {
            g_count = 0u;
            asm volatile("st.release.gpu.b32 [%0], %1;" :: "l"(&g_gen), "r"(target) : "memory");
        } else {
            unsigned int cur;
            do {
                __nanosleep(20);
                asm volatile("ld.acquire.gpu.b32 %0, [%1];" : "=r"(cur) : "l"(&g_gen) : "memory");
            } while ((int)(cur - target) < 0);
        }
    }
    __syncthreads();
}
__device__ __forceinline__ void wait_flag(const unsigned int* f, unsigned int tgt) {
    unsigned int v;
    asm volatile("ld.acquire.gpu.b32 %0, [%1];" : "=r"(v) : "l"(f) : "memory");
    while ((int)(v - tgt) < 0) {
        __nanosleep(32);
        asm volatile("ld.acquire.gpu.b32 %0, [%1];" : "=r"(v) : "l"(f) : "memory");
    }
}

// warp-private prefetch: warp w's 2KB row-slice (rows 16w..16w+15) of one chunk
__device__ __forceinline__ void prefetch_slice(uint32_t dst_stage, const unsigned char* src,
                                               uint32_t wslice, int lane) {
#pragma unroll
    for (int i = 0; i < 4; i++) {
        uint32_t off = wslice + (uint32_t)lane * 16u + (uint32_t)i * 512u;
        asm volatile("cp.async.cg.shared.global [%0], [%1], 16;"
                     :: "r"(dst_stage + off), "l"(src + off) : "memory");
    }
    asm volatile("cp.async.commit_group;" ::: "memory");
}

__device__ __forceinline__ void ldmx4(uint32_t addr, uint32_t* a) {
    asm volatile("ldmatrix.sync.aligned.m8n8.x4.shared.b16 {%0,%1,%2,%3}, [%4];"
                 : "=r"(a[0]), "=r"(a[1]), "=r"(a[2]), "=r"(a[3]) : "r"(addr));
}
__device__ __forceinline__ void mma16816(float* d, const uint32_t* a, uint32_t b0, uint32_t b1) {
    asm volatile(
        "mma.sync.aligned.m16n8k16.row.col.f32.f16.f16.f32 "
        "{%0,%1,%2,%3}, {%4,%5,%6,%7}, {%8,%9}, {%0,%1,%2,%3};"
        : "+f"(d[0]), "+f"(d[1]), "+f"(d[2]), "+f"(d[3])
        : "r"(a[0]), "r"(a[1]), "r"(a[2]), "r"(a[3]), "r"(b0), "r"(b1));
}
__device__ __forceinline__ uint32_t pack_h2(float lo, float hi) {
    uint32_t r;
    asm("cvt.rn.f16x2.f32 %0, %1, %2;" : "=r"(r) : "f"(hi), "f"(lo));
    return r;
}

// consume one staged chunk: 4 ldmatrix + 8 LDS.64 + 8 HMMA
__device__ __forceinline__ void consume_chunk(uint32_t sa, uint32_t wb,
                                              uint32_t abase, int lane,
                                              float* D0, float* D1) {
#pragma unroll
    for (int ks = 0; ks < 4; ++ks) {
        uint32_t ao = sw128(abase + (uint32_t)ks * 32u);
        uint32_t a[4];
        ldmx4(sa + ao, a);
#pragma unroll
        for (int nt = 0; nt < 2; ++nt) {
            uint32_t fb = wb + (uint32_t)(ks * 2 + nt) * 256u + (uint32_t)lane * 8u;
            uint32_t bh0, bh1;
            asm("ld.shared.v2.b32 {%0,%1}, [%2];" : "=r"(bh0), "=r"(bh1) : "r"(fb));
            float* D = nt ? D1 : D0;
            mma16816(D, a, bh0, bh1);
        }
    }
}

__global__ void reset_flags_kernel() {
    if (threadIdx.x < 64) g_flag[threadIdx.x] = 16u;   // h_0 ready baseline
}

__global__ void __launch_bounds__(NT, 1) lstm_persistent(
    const float* __restrict__ ts,
    const float* __restrict__ w_ih_enc, const float* __restrict__ w_hh_enc,
    const float* __restrict__ b_ih_enc, const float* __restrict__ b_hh_enc,
    const float* __restrict__ w_ih_dec, const float* __restrict__ w_hh_dec,
    const float* __restrict__ b_ih_dec, const float* __restrict__ b_hh_dec,
    const float* __restrict__ w_out, const float* __restrict__ b_out,
    float* __restrict__ out)
{
    extern __shared__ unsigned char smem[];
    const int tid = threadIdx.x;
    const int cid = blockIdx.x;
    const int jb = cid * 4;
    const int gidx = cid >> 4;
    const uint32_t sb = (uint32_t)__cvta_generic_to_shared(smem);

    // ======== INIT: encoder B fragments, fp16 ========
    for (int e = tid; e < 9 * 4 * 2 * 32; e += NT) {
        int lane = e & 31, rem = e >> 5;
        int nt = rem & 1, ks = (rem >> 1) & 3, ch = rem >> 3;
        int gid = lane >> 2, tig = lane & 3;
        int n = nt * 8 + gid, jl = n >> 2, q = n & 3;
        int row = q * HH + jb + jl;
        float v[4];
#pragma unroll
        for (int d = 0; d < 4; ++d) {
            int kin = ks * 16 + 2 * tig + ((d & 2) ? 8 : 0) + (d & 1);
            v[d] = (ch < 8) ? w_hh_enc[(size_t)row * HH + ch * 64 + kin]
                            : w_ih_enc[(size_t)row * FF + kin];
        }
        uint32_t base = (uint32_t)(ch * 8 + ks * 2 + nt) * 256u + (uint32_t)lane * 8u;
        uint32_t* ph = (uint32_t*)(smem + OFF_WBE + base);
        ph[0] = pack_h2(v[0], v[1]); ph[1] = pack_h2(v[2], v[3]);
    }
    // ======== INIT: decoder fused B fragments (W_eff = w_hh + w_ih @ w_out) ========
    for (int e = tid; e < 8 * 4 * 2 * 32; e += NT) {
        int lane = e & 31, rem = e >> 5;
        int nt = rem & 1, ks = (rem >> 1) & 3, ch = rem >> 3;
        int gid = lane >> 2, tig = lane & 3;
        int n = nt * 8 + gid, jl = n >> 2, q = n & 3;
        int row = q * HH + jb + jl;
        const float* wr = w_ih_dec + (size_t)row * FF;
        float v[4];
#pragma unroll
        for (int d = 0; d < 4; ++d) {
            int k = ch * 64 + ks * 16 + 2 * tig + ((d & 2) ? 8 : 0) + (d & 1);
            float acc = w_hh_dec[(size_t)row * HH + k];
#pragma unroll 8
            for (int f = 0; f < FF; ++f) acc += wr[f] * w_out[(size_t)f * HH + k];
            v[d] = acc;
        }
        uint32_t base = (uint32_t)(ch * 8 + ks * 2 + nt) * 256u + (uint32_t)lane * 8u;
        uint32_t* ph = (uint32_t*)(smem + OFF_WBD + base);
        ph[0] = pack_h2(v[0], v[1]); ph[1] = pack_h2(v[2], v[3]);
    }
    // biases [jl][q]
    if (tid < 16) {
        int jl = tid >> 2, q = tid & 3;
        int row = q * HH + jb + jl;
        ((float*)(smem + OFF_BE))[jl * 4 + q] = b_ih_enc[row] + b_hh_enc[row];
        float v = b_ih_dec[row] + b_hh_dec[row];
        const float* wr = w_ih_dec + (size_t)row * FF;
#pragma unroll 8
        for (int f = 0; f < FF; ++f) v += wr[f] * b_out[f];
        ((float*)(smem + OFF_BD))[jl * 4 + q] = v;
    }
    // x tiles: [t][b*128B] fp16, swizzled; 8 t per CTA
    for (int tt = 0; tt < TT / NB; ++tt) {
        int t = cid * (TT / NB) + tt;
        for (int idx = tid; idx < BB * 16; idx += NT) {
            int b = idx >> 4, f4 = (idx & 15) * 4;
            float v0 = ts[((size_t)b * TT + t) * FF + f4];
            float v1 = ts[((size_t)b * TT + t) * FF + f4 + 1];
            float v2 = ts[((size_t)b * TT + t) * FF + f4 + 2];
            float v3 = ts[((size_t)b * TT + t) * FF + f4 + 3];
            uint32_t o = sw128((uint32_t)(b * 128 + f4 * 2));
            *(uint2*)(g_xh + (size_t)t * 16384 + o) =
                make_uint2(pack_h2(v0, v1), pack_h2(v2, v3));
        }
    }
    // zero own h_0 slice (4 cols x 128 b)
    if (tid < 128) {
        uint32_t o = sw128((uint32_t)(tid * 128 + (cid & 15) * 8));
        *(uint2*)(g_hh[0] + (size_t)gidx * 16384 + o) = make_uint2(0, 0);
    }
    if (cid == 0) {
        for (int idx = tid; idx < HH * FF; idx += NT) {
            int j = idx >> 6, f = idx & 63;
            g_woutT[j * FF + f] = w_out[(size_t)f * HH + j];
        }
    }
    grid_barrier_init();

    // ======== persistent recurrence: fully warp-autonomous ========
    const int w = tid >> 5, lane = tid & 31;
    const int gid = lane >> 2, tig = lane & 3;
    const uint32_t abase = (uint32_t)(((w << 4) + (lane & 15)) * 128 + ((lane >> 4) & 1) * 16);
    const uint32_t wslice = (uint32_t)w * 2048u;   // warp's row-slice byte offset in tile
    unsigned int* const myflag = &g_flag[gidx * 8 + w];     // this warp publishes here
    // lane l (l<8) polls chunk l's flag for this warp index
    const unsigned int* const pollflag = &g_flag[(lane & 7) * 8 + w];

    float c0s = 0.0f, c8s = 0.0f;

    for (int s = 0; s < 2 * TT; ++s) {
        const bool enc = (s < TT);
        const int nc = enc ? 9 : 8;
        if (s == TT) { c0s = 0.0f; c8s = 0.0f; }
        const unsigned int tgt = 16u * (unsigned)(s + 1);

        // per-warp flag wait: lanes 0..7 poll the 8 per-warp chunk flags
        if (lane < 8) wait_flag(pollflag, tgt);
        __syncwarp();

        const unsigned char* hh = g_hh[s & 1];
#define SRC(i) (enc ? ((i) == 0 ? g_xh + (size_t)s * 16384 : hh + (size_t)((i) - 1) * 16384) \
                    : hh + (size_t)(i) * 16384)

        prefetch_slice(sb + OFF_A, SRC(0), wslice, lane);
        prefetch_slice(sb + OFF_A + 16384u, SRC(1), wslice, lane);

        float D0[4] = {0, 0, 0, 0}, D1[4] = {0, 0, 0, 0};

        for (int i = 0; i < nc; ++i) {
            if (i + 1 < nc) {
                asm volatile("cp.async.wait_group 1;" ::: "memory");
            } else {
                asm volatile("cp.async.wait_group 0;" ::: "memory");
            }
            if (i + 2 < nc) {
                prefetch_slice(sb + OFF_A + (uint32_t)((i + 2) % 3) * 16384u,
                               SRC(i + 2), wslice, lane);
            }
            int ch = enc ? (i == 0 ? 8 : i - 1) : i;
            uint32_t wb = sb + (enc ? OFF_WBE : OFF_WBD) + (uint32_t)ch * 2048u;
            consume_chunk(sb + OFF_A + (uint32_t)(i % 3) * 16384u, wb, abase, lane, D0, D1);
        }
#undef SRC

        // ---- epilogue: gate pairing via shfl, cell update ----
        bool ev = ((tig & 1) == 0);
        float s0 = ev ? D1[0] : D0[0];
        float s1 = ev ? D1[1] : D0[1];
        float s2 = ev ? D1[2] : D0[2];
        float s3 = ev ? D1[3] : D0[3];
        float r0 = __shfl_xor_sync(0xffffffffu, s0, 1);
        float r1 = __shfl_xor_sync(0xffffffffu, s1, 1);
        float r2 = __shfl_xor_sync(0xffffffffu, s2, 1);
        float r3 = __shfl_xor_sync(0xffffffffu, s3, 1);
        float gi0, gf0, gi8, gf8, gg0, go0, gg8, go8;
        int jl;
        if (ev) {
            gi0 = D0[0]; gf0 = D0[1]; gi8 = D0[2]; gf8 = D0[3];
            gg0 = r0; go0 = r1; gg8 = r2; go8 = r3;
            jl = tig >> 1;
        } else {
            gi0 = r0; gf0 = r1; gi8 = r2; gf8 = r3;
            gg0 = D1[0]; go0 = D1[1]; gg8 = D1[2]; go8 = D1[3];
            jl = (tig >> 1) + 2;
        }
        float4 bi = ((const float4*)(smem + (enc ? OFF_BE : OFF_BD)))[jl];
        float iv0 = sigf(gi0 + bi.x), fv0 = sigf(gf0 + bi.y);
        float gv0 = tanhfast(gg0 + bi.z), ov0 = sigf(go0 + bi.w);
        float iv8 = sigf(gi8 + bi.x), fv8 = sigf(gf8 + bi.y);
        float gv8 = tanhfast(gg8 + bi.z), ov8 = sigf(go8 + bi.w);
        c0s = fv0 * c0s + iv0 * gv0;
        c8s = fv8 * c8s + iv8 * gv8;
        float h0 = ov0 * tanhfast(c0s);
        float h8 = ov8 * tanhfast(c8s);

        int b0r = (w << 4) + gid;
        uint32_t colb = (uint32_t)((((cid & 15) << 2) + jl) << 1);
        uint32_t o0 = sw128((uint32_t)(b0r * 128) + colb);
        uint32_t o8 = sw128((uint32_t)((b0r + 8) * 128) + colb);
        int nb2 = (s + 1) & 1;
        size_t tb = (size_t)gidx * 16384;
        *(__half*)(g_hh[nb2] + tb + o0) = __float2half_rn(h0);
        *(__half*)(g_hh[nb2] + tb + o8) = __float2half_rn(h8);
        if (s >= TT - 1 && s < 2 * TT - 1) {
            int kd = s - (TT - 1);
            float* hb = g_hist + ((size_t)kd * HH + (jb + jl)) * BB;
            hb[b0r] = h0;
            hb[b0r + 8] = h8;
        }
        // warp-scope release: this warp's h-slice is complete
        __threadfence();
        __syncwarp();
        if (lane == 0) atomicAdd(myflag, 1u);
    }
}

// ============ final y pass: out[b][T-1-kd][:] = hist[kd]·w_outT + b_out ============
__global__ void __launch_bounds__(128) y_final(const float* __restrict__ b_out,
                                               float* __restrict__ out) {
    const int kd = blockIdx.x;
    const int b = threadIdx.x;
    ull acc[32];
#pragma unroll
    for (int q = 0; q < 32; ++q) {
        float2 bo = *(const float2*)(b_out + 2 * q);
        asm("mov.b64 %0, {%1, %2};" : "=l"(acc[q]) : "f"(bo.x), "f"(bo.y));
    }
    const float* hp = g_hist + (size_t)kd * HH * BB + b;
#pragma unroll 4
    for (int j = 0; j < HH; ++j) {
        float hv = hp[(size_t)j * BB];
        ull h2;
        asm("mov.b64 %0, {%1, %2};" : "=l"(h2) : "f"(hv), "f"(hv));
        const ulonglong2* wp = (const ulonglong2*)(g_woutT + j * FF);
#pragma unroll
        for (int q = 0; q < 16; ++q) {
            ulonglong2 w2 = wp[q];
            asm("fma.rn.f32x2 %0, %1, %2, %0;" : "+l"(acc[2 * q]) : "l"(w2.x), "l"(h2));
            asm("fma.rn.f32x2 %0, %1, %2, %0;" : "+l"(acc[2 * q + 1]) : "l"(w2.y), "l"(h2));
        }
    }
    float* dst = out + ((size_t)b * TT + (TT - 1 - kd)) * FF;
#pragma unroll
    for (int q = 0; q < 16; ++q) {
        float2 a = *(float2*)&acc[2 * q];
        float2 bq = *(float2*)&acc[2 * q + 1];
        *(float4*)(dst + 4 * q) = make_float4(a.x, a.y, bq.x, bq.y);
    }
}

// ---------------- launch ----------------
extern "C" void kernel_launch(void* const* d_in, const int* in_sizes, int n_in,
                              void* d_out, int out_size) {
    (void)in_sizes; (void)n_in; (void)out_size;
    const float* ts       = (const float*)d_in[0];
    const float* w_ih_enc = (const float*)d_in[1];
    const float* w_hh_enc = (const float*)d_in[2];
    const float* b_ih_enc = (const float*)d_in[3];
    const float* b_hh_enc = (const float*)d_in[4];
    const float* w_ih_dec = (const float*)d_in[5];
    const float* w_hh_dec = (const float*)d_in[6];
    const float* b_ih_dec = (const float*)d_in[7];
    const float* b_hh_dec = (const float*)d_in[8];
    const float* w_out    = (const float*)d_in[9];
    const float* b_out    = (const float*)d_in[10];
    float* out = (float*)d_out;

    static bool attr_set = false;
    if (!attr_set) {
        cudaFuncSetAttribute(lstm_persistent,
                             cudaFuncAttributeMaxDynamicSharedMemorySize, SMEM_BYTES);
        attr_set = true;
    }
    reset_flags_kernel<<<1, 64>>>();
    lstm_persistent<<<NB, NT, SMEM_BYTES>>>(
        ts, w_ih_enc, w_hh_enc, b_ih_enc, b_hh_enc,
        w_ih_dec, w_hh_dec, b_ih_dec, b_hh_dec, w_out, b_out, out);
    y_final<<<TT, 128>>>(b_out, out);
}